// round 9
// baseline (speedup 1.0000x reference)
#include <cuda_runtime.h>
#include <cuda_bf16.h>
#include <cstdint>

// ---------------------------------------------------------------------------
// PointGenerator: X_world = M_c @ [x*d, y*d, d, 1],  M = E_ @ n2r @ K_^-1 (3x4)
//   M[i] = { e_i0/f, -e_i1/f, -M[i].x*cx - M[i].y*cy - e_i2, e_i3 } ; w == 1
//
// R8: PERSISTENT blocks (4/SM) + 2-stage TMA double buffer.
// Cameras built once per block; steady-state TMA waits hidden behind the
// other stage's compute. Direct coalesced STG.128 output.
// ---------------------------------------------------------------------------

#define MAX_CAMS  256
#define NTHREADS  256
#define STAGE_PTS 1024          // points per pipeline stage
#define NSTAGES   2

__device__ __forceinline__ uint32_t smem_u32(const void* p) {
    uint32_t a;
    asm("{ .reg .u64 t; cvta.to.shared.u64 t, %1; cvt.u32.u64 %0, t; }"
        : "=r"(a) : "l"(p));
    return a;
}
__device__ __forceinline__ void mbar_init(uint32_t mbar, uint32_t cnt) {
    asm volatile("mbarrier.init.shared.b64 [%0], %1;" :: "r"(mbar), "r"(cnt) : "memory");
}
__device__ __forceinline__ void mbar_expect_tx(uint32_t mbar, uint32_t bytes) {
    asm volatile("mbarrier.arrive.expect_tx.shared.b64 _, [%0], %1;"
                 :: "r"(mbar), "r"(bytes) : "memory");
}
__device__ __forceinline__ void mbar_wait(uint32_t mbar, uint32_t parity) {
    uint32_t done;
    asm volatile(
        "{ .reg .pred p;\n"
        "  mbarrier.try_wait.parity.acquire.cta.shared::cta.b64 p, [%1], %2;\n"
        "  selp.b32 %0, 1, 0, p; }"
        : "=r"(done) : "r"(mbar), "r"(parity) : "memory");
    if (!done) {
        asm volatile(
            "{ .reg .pred P1;\n"
            "WAIT_%=:\n"
            "  mbarrier.try_wait.parity.acquire.cta.shared::cta.b64 P1, [%0], %1, 0x989680;\n"
            "  @P1 bra.uni DONE_%=;\n"
            "  bra.uni WAIT_%=;\n"
            "DONE_%=: }"
            :: "r"(mbar), "r"(parity) : "memory");
    }
}
__device__ __forceinline__ void bulk_load_g2s(uint32_t smem_dst, const void* gmem_src,
                                              uint32_t bytes, uint32_t mbar) {
    asm volatile(
        "cp.async.bulk.shared::cta.global.mbarrier::complete_tx::bytes [%0], [%1], %2, [%3];"
        :: "r"(smem_dst), "l"(gmem_src), "r"(bytes), "r"(mbar) : "memory");
}

struct Stage {
    int   pidx[STAGE_PTS * 3];   // 12 KB
    float depth[STAGE_PTS];      //  4 KB
};
struct SmemLayout {
    float4 cam[MAX_CAMS * 3];    // 12 KB
    Stage  st[NSTAGES];          // 32 KB
    alignas(8) unsigned long long mbar[NSTAGES];
};                               // ~45 KB total (static smem, <48 KB OK)

__device__ __forceinline__ float4 transform(const float4* __restrict__ s_cam,
                                            int c, float xf, float yf, float dd) {
    float xd = xf * dd;
    float yd = yf * dd;
    float4 r0 = s_cam[c * 3 + 0];
    float4 r1 = s_cam[c * 3 + 1];
    float4 r2 = s_cam[c * 3 + 2];
    float4 o;
    o.x = fmaf(r0.x, xd, fmaf(r0.y, yd, fmaf(r0.z, dd, r0.w)));
    o.y = fmaf(r1.x, xd, fmaf(r1.y, yd, fmaf(r1.z, dd, r1.w)));
    o.z = fmaf(r2.x, xd, fmaf(r2.y, yd, fmaf(r2.z, dd, r2.w)));
    o.w = 1.0f;
    return o;
}

__global__ void __launch_bounds__(NTHREADS, 4)
point_gen_kernel(const int*   __restrict__ pidx,   // [N,3] i32
                 const float* __restrict__ depth,  // [N]   f32
                 const float* __restrict__ c2w,    // [C,3,4] f32
                 const float* __restrict__ intr,   // [C,3,3] f32
                 float*       __restrict__ out,    // [N,4] f32
                 int npoints, int num_cams, int ntiles) {
    __shared__ SmemLayout sm;

    const int tid = threadIdx.x;

    uint32_t mbar_a[NSTAGES];
    mbar_a[0] = smem_u32(&sm.mbar[0]);
    mbar_a[1] = smem_u32(&sm.mbar[1]);
    uint32_t st_pidx[NSTAGES], st_dep[NSTAGES];
    st_pidx[0] = smem_u32(sm.st[0].pidx);  st_dep[0] = smem_u32(sm.st[0].depth);
    st_pidx[1] = smem_u32(sm.st[1].pidx);  st_dep[1] = smem_u32(sm.st[1].depth);

    if (tid == 0) { mbar_init(mbar_a[0], 1); mbar_init(mbar_a[1], 1); }
    __syncthreads();

    // --- prologue: prefetch first NSTAGES tiles owned by this block ---
    if (tid == 0) {
#pragma unroll
        for (int s = 0; s < NSTAGES; s++) {
            int tile = blockIdx.x + s * gridDim.x;
            if (tile < ntiles) {
                int base = tile * STAGE_PTS;
                int pts  = npoints - base; if (pts > STAGE_PTS) pts = STAGE_PTS;
                int bulk = pts & ~3;
                if (bulk > 0) {
                    mbar_expect_tx(mbar_a[s], (uint32_t)bulk * 16u);
                    bulk_load_g2s(st_pidx[s], pidx + (size_t)base * 3,
                                  (uint32_t)bulk * 12u, mbar_a[s]);
                    bulk_load_g2s(st_dep[s], depth + base,
                                  (uint32_t)bulk * 4u, mbar_a[s]);
                } else {
                    mbar_expect_tx(mbar_a[s], 0);  // keep parity sequence intact
                }
            }
        }
    }

    // --- camera matrices (once per block), overlapping prologue TMA ---
    const float4* c2w4 = (const float4*)c2w;
    for (int c = tid; c < num_cams; c += NTHREADS) {
        float f  = __ldg(intr + c * 9 + 0);
        float cx = __ldg(intr + c * 9 + 2);
        float cy = __ldg(intr + c * 9 + 5);
        float invf = 1.0f / f;
#pragma unroll
        for (int i = 0; i < 3; i++) {
            float4 e = c2w4[c * 3 + i];        // {e0, e1, e2, t}
            float4 r;
            r.x = e.x * invf;
            r.y = -e.y * invf;
            r.z = fmaf(-r.x, cx, fmaf(-r.y, cy, -e.z));
            r.w = e.w;
            sm.cam[c * 3 + i] = r;
        }
    }
    __syncthreads();

    float4* out4 = (float4*)out;
    int par[NSTAGES] = {0, 0};

    // --- steady-state pipeline ---
    int s = 0;
    for (int tile = blockIdx.x; tile < ntiles; tile += gridDim.x, s ^= 1) {
        int base = tile * STAGE_PTS;
        int pts  = npoints - base; if (pts > STAGE_PTS) pts = STAGE_PTS;
        int bulk = pts & ~3;

        mbar_wait(mbar_a[s], par[s]);
        par[s] ^= 1;

        const Stage& st = sm.st[s];
        if (pts == STAGE_PTS) {
            // fast path: branch-free, 2-point load batching
#pragma unroll
            for (int j = 0; j < STAGE_PTS / NTHREADS; j += 2) {
                int p0 = tid + (j + 0) * NTHREADS;
                int p1 = tid + (j + 1) * NTHREADS;
                int   c0 = st.pidx[3 * p0 + 0];
                int   c1 = st.pidx[3 * p1 + 0];
                float y0 = (float)st.pidx[3 * p0 + 1];
                float y1 = (float)st.pidx[3 * p1 + 1];
                float x0 = (float)st.pidx[3 * p0 + 2];
                float x1 = (float)st.pidx[3 * p1 + 2];
                float d0 = st.depth[p0];
                float d1 = st.depth[p1];
                float4 o0 = transform(sm.cam, c0, x0, y0, d0);
                float4 o1 = transform(sm.cam, c1, x1, y1, d1);
                out4[base + p0] = o0;
                out4[base + p1] = o1;
            }
        } else {
            // partial (last) tile
#pragma unroll
            for (int j = 0; j < STAGE_PTS / NTHREADS; j++) {
                int p = tid + j * NTHREADS;
                if (p < bulk) {
                    int   c  = st.pidx[3 * p + 0];
                    float yf = (float)st.pidx[3 * p + 1];
                    float xf = (float)st.pidx[3 * p + 2];
                    out4[base + p] = transform(sm.cam, c, xf, yf, st.depth[p]);
                }
            }
            for (int p = base + bulk + tid; p < base + pts; p += NTHREADS) {
                int   c  = pidx[3 * p + 0];
                float yf = (float)pidx[3 * p + 1];
                float xf = (float)pidx[3 * p + 2];
                out4[p] = transform(sm.cam, c, xf, yf, depth[p]);
            }
        }

        __syncthreads();   // all threads done reading stage s

        // refill stage s with tile + NSTAGES*grid
        int ntile = tile + NSTAGES * gridDim.x;
        if (tid == 0 && ntile < ntiles) {
            int nbase = ntile * STAGE_PTS;
            int npts  = npoints - nbase; if (npts > STAGE_PTS) npts = STAGE_PTS;
            int nbulk = npts & ~3;
            if (nbulk > 0) {
                mbar_expect_tx(mbar_a[s], (uint32_t)nbulk * 16u);
                bulk_load_g2s(st_pidx[s], pidx + (size_t)nbase * 3,
                              (uint32_t)nbulk * 12u, mbar_a[s]);
                bulk_load_g2s(st_dep[s], depth + nbase,
                              (uint32_t)nbulk * 4u, mbar_a[s]);
            } else {
                mbar_expect_tx(mbar_a[s], 0);
            }
        }
    }
}

extern "C" void kernel_launch(void* const* d_in, const int* in_sizes, int n_in,
                              void* d_out, int out_size) {
    // metadata order: point_indices[N,3] i32, depth[N,1] f32, image_coords (unused),
    //                 camera_to_worlds[C,3,4] f32, intrinsics[C,3,3] f32
    const int*   pidx  = (const int*)d_in[0];
    const float* depth = (const float*)d_in[1];
    const float* c2w   = (const float*)d_in[3];
    const float* intr  = (const float*)d_in[4];
    float*       out   = (float*)d_out;

    int npoints  = in_sizes[0] / 3;
    int num_cams = in_sizes[3] / 12;
    if (num_cams > MAX_CAMS) num_cams = MAX_CAMS;

    int ntiles = (npoints + STAGE_PTS - 1) / STAGE_PTS;
    int blocks = 148 * 4;
    if (blocks > ntiles) blocks = ntiles;
    point_gen_kernel<<<blocks, NTHREADS>>>(pidx, depth, c2w, intr, out,
                                           npoints, num_cams, ntiles);
}

// round 13
// speedup vs baseline: 1.0133x; 1.0133x over previous
#include <cuda_runtime.h>
#include <cuda_bf16.h>
#include <cstdint>

// ---------------------------------------------------------------------------
// PointGenerator: X_world = M_c @ [x*d, y*d, d, 1],  M = E_ @ n2r @ K_^-1 (3x4)
//   M[i] = { e_i0/f, -e_i1/f, -M[i].x*cx - M[i].y*cy - e_i2, e_i3 } ; w == 1
//
// R9: PER-WARP TMA pipelines. Each warp has a private 2-stage ring + private
// mbarriers; no block-wide sync in the steady loop -> warps run out of phase
// and the L1 duty cycle rises (R6-R8 were convoy-limited at 52% L1 duty).
// ---------------------------------------------------------------------------

#define MAX_CAMS 256
#define NTHREADS 256
#define WARPS    8
#define CHUNK    128     // points per warp-chunk
#define NSTAGES  2
#define PPT      4       // points per thread per chunk (CHUNK/32)

__device__ __forceinline__ uint32_t smem_u32(const void* p) {
    uint32_t a;
    asm("{ .reg .u64 t; cvta.to.shared.u64 t, %1; cvt.u32.u64 %0, t; }"
        : "=r"(a) : "l"(p));
    return a;
}
__device__ __forceinline__ void mbar_init(uint32_t mbar, uint32_t cnt) {
    asm volatile("mbarrier.init.shared.b64 [%0], %1;" :: "r"(mbar), "r"(cnt) : "memory");
}
__device__ __forceinline__ void mbar_expect_tx(uint32_t mbar, uint32_t bytes) {
    asm volatile("mbarrier.arrive.expect_tx.shared.b64 _, [%0], %1;"
                 :: "r"(mbar), "r"(bytes) : "memory");
}
__device__ __forceinline__ void mbar_wait(uint32_t mbar, uint32_t parity) {
    uint32_t done;
    asm volatile(
        "{ .reg .pred p;\n"
        "  mbarrier.try_wait.parity.acquire.cta.shared::cta.b64 p, [%1], %2;\n"
        "  selp.b32 %0, 1, 0, p; }"
        : "=r"(done) : "r"(mbar), "r"(parity) : "memory");
    if (!done) {
        asm volatile(
            "{ .reg .pred P1;\n"
            "WAIT_%=:\n"
            "  mbarrier.try_wait.parity.acquire.cta.shared::cta.b64 P1, [%0], %1, 0x989680;\n"
            "  @P1 bra.uni DONE_%=;\n"
            "  bra.uni WAIT_%=;\n"
            "DONE_%=: }"
            :: "r"(mbar), "r"(parity) : "memory");
    }
}
__device__ __forceinline__ void bulk_load_g2s(uint32_t smem_dst, const void* gmem_src,
                                              uint32_t bytes, uint32_t mbar) {
    asm volatile(
        "cp.async.bulk.shared::cta.global.mbarrier::complete_tx::bytes [%0], [%1], %2, [%3];"
        :: "r"(smem_dst), "l"(gmem_src), "r"(bytes), "r"(mbar) : "memory");
}

struct alignas(16) WStage {
    int   pidx[CHUNK * 3];   // 1536 B
    float depth[CHUNK];      //  512 B
};
struct SmemLayout {
    float4 cam[MAX_CAMS * 3];                        // 12 KB
    WStage st[WARPS][NSTAGES];                       // 32 KB
    alignas(8) unsigned long long mbar[WARPS][NSTAGES];
};                                                   // ~44.3 KB static

__device__ __forceinline__ float4 transform(const float4* __restrict__ s_cam,
                                            int c, float xf, float yf, float dd) {
    float xd = xf * dd;
    float yd = yf * dd;
    float4 r0 = s_cam[c * 3 + 0];
    float4 r1 = s_cam[c * 3 + 1];
    float4 r2 = s_cam[c * 3 + 2];
    float4 o;
    o.x = fmaf(r0.x, xd, fmaf(r0.y, yd, fmaf(r0.z, dd, r0.w)));
    o.y = fmaf(r1.x, xd, fmaf(r1.y, yd, fmaf(r1.z, dd, r1.w)));
    o.z = fmaf(r2.x, xd, fmaf(r2.y, yd, fmaf(r2.z, dd, r2.w)));
    o.w = 1.0f;
    return o;
}

__global__ void __launch_bounds__(NTHREADS, 5)
point_gen_kernel(const int*   __restrict__ pidx,   // [N,3] i32
                 const float* __restrict__ depth,  // [N]   f32
                 const float* __restrict__ c2w,    // [C,3,4] f32
                 const float* __restrict__ intr,   // [C,3,3] f32
                 float*       __restrict__ out,    // [N,4] f32
                 int npoints, int num_cams, int nchunks) {
    __shared__ SmemLayout sm;

    const int tid  = threadIdx.x;
    const int wid  = tid >> 5;
    const int lane = tid & 31;
    const int gw     = blockIdx.x * WARPS + wid;   // this warp's first chunk
    const int stride = gridDim.x * WARPS;

    uint32_t mbar_a[NSTAGES];
    mbar_a[0] = smem_u32(&sm.mbar[wid][0]);
    mbar_a[1] = smem_u32(&sm.mbar[wid][1]);
    uint32_t st_p[NSTAGES], st_d[NSTAGES];
    st_p[0] = smem_u32(sm.st[wid][0].pidx);  st_d[0] = smem_u32(sm.st[wid][0].depth);
    st_p[1] = smem_u32(sm.st[wid][1].pidx);  st_d[1] = smem_u32(sm.st[wid][1].depth);

    // --- per-warp mbar init + prologue TMA (lane 0 of each warp) ---
    if (lane == 0) {
        mbar_init(mbar_a[0], 1);
        mbar_init(mbar_a[1], 1);
        asm volatile("fence.proxy.async.shared::cta;" ::: "memory");
#pragma unroll
        for (int s = 0; s < NSTAGES; s++) {
            int chunk = gw + s * stride;
            if (chunk < nchunks) {
                int base = chunk * CHUNK;
                int pts  = npoints - base; if (pts > CHUNK) pts = CHUNK;
                int bulk = pts & ~3;
                if (bulk > 0) {
                    mbar_expect_tx(mbar_a[s], (uint32_t)bulk * 16u);
                    bulk_load_g2s(st_p[s], pidx + (size_t)base * 3,
                                  (uint32_t)bulk * 12u, mbar_a[s]);
                    bulk_load_g2s(st_d[s], depth + base,
                                  (uint32_t)bulk * 4u, mbar_a[s]);
                }
            }
        }
    }

    // --- camera matrices, once per block (overlaps prologue TMA) ---
    const float4* c2w4 = (const float4*)c2w;
    for (int c = tid; c < num_cams; c += NTHREADS) {
        float f  = __ldg(intr + c * 9 + 0);
        float cx = __ldg(intr + c * 9 + 2);
        float cy = __ldg(intr + c * 9 + 5);
        float invf = 1.0f / f;
#pragma unroll
        for (int i = 0; i < 3; i++) {
            float4 e = c2w4[c * 3 + i];        // {e0, e1, e2, t}
            float4 r;
            r.x = e.x * invf;
            r.y = -e.y * invf;
            r.z = fmaf(-r.x, cx, fmaf(-r.y, cy, -e.z));
            r.w = e.w;
            sm.cam[c * 3 + i] = r;
        }
    }
    __syncthreads();   // cameras ready; the ONLY block-wide sync

    float4* out4 = (float4*)out;
    int par0 = 0, par1 = 0;

    // --- per-warp steady-state pipeline (no block syncs) ---
    int s = 0;
    for (int chunk = gw; chunk < nchunks; chunk += stride, s ^= 1) {
        int base = chunk * CHUNK;
        int pts  = npoints - base; if (pts > CHUNK) pts = CHUNK;
        int bulk = pts & ~3;

        uint32_t mb = (s == 0) ? mbar_a[0] : mbar_a[1];
        int par = (s == 0) ? par0 : par1;
        if (bulk > 0) mbar_wait(mb, par);
        if (s == 0) par0 ^= 1; else par1 ^= 1;

        const WStage& st = sm.st[wid][s];
        if (pts == CHUNK) {
            // branch-free: thread handles points lane, lane+32, lane+64, lane+96
            // -> dense coalesced STG.128; scalar LDS stride-3 conflict-free.
#pragma unroll
            for (int j = 0; j < PPT; j += 2) {
                int p0 = lane + (j + 0) * 32;
                int p1 = lane + (j + 1) * 32;
                int   c0 = st.pidx[3 * p0 + 0];
                int   c1 = st.pidx[3 * p1 + 0];
                float y0 = (float)st.pidx[3 * p0 + 1];
                float y1 = (float)st.pidx[3 * p1 + 1];
                float x0 = (float)st.pidx[3 * p0 + 2];
                float x1 = (float)st.pidx[3 * p1 + 2];
                float d0 = st.depth[p0];
                float d1 = st.depth[p1];
                float4 o0 = transform(sm.cam, c0, x0, y0, d0);
                float4 o1 = transform(sm.cam, c1, x1, y1, d1);
                out4[base + p0] = o0;
                out4[base + p1] = o1;
            }
        } else {
            // partial last chunk
#pragma unroll
            for (int j = 0; j < PPT; j++) {
                int p = lane + j * 32;
                if (p < bulk) {
                    int   c  = st.pidx[3 * p + 0];
                    float yf = (float)st.pidx[3 * p + 1];
                    float xf = (float)st.pidx[3 * p + 2];
                    out4[base + p] = transform(sm.cam, c, xf, yf, st.depth[p]);
                }
            }
            for (int p = base + bulk + lane; p < base + pts; p += 32) {
                int   c  = pidx[3 * p + 0];
                float yf = (float)pidx[3 * p + 1];
                float xf = (float)pidx[3 * p + 2];
                out4[p] = transform(sm.cam, c, xf, yf, depth[p]);
            }
        }

        __syncwarp();   // all lanes done reading stage s (warp-local, cheap)

        // refill stage s with chunk + 2*stride (lane 0)
        int nchunk = chunk + NSTAGES * stride;
        if (lane == 0 && nchunk < nchunks) {
            int nbase = nchunk * CHUNK;
            int npts  = npoints - nbase; if (npts > CHUNK) npts = CHUNK;
            int nbulk = npts & ~3;
            if (nbulk > 0) {
                mbar_expect_tx(mb, (uint32_t)nbulk * 16u);
                bulk_load_g2s(st_p[s], pidx + (size_t)nbase * 3,
                              (uint32_t)nbulk * 12u, mb);
                bulk_load_g2s(st_d[s], depth + nbase,
                              (uint32_t)nbulk * 4u, mb);
            }
        }
    }
}

extern "C" void kernel_launch(void* const* d_in, const int* in_sizes, int n_in,
                              void* d_out, int out_size) {
    // metadata order: point_indices[N,3] i32, depth[N,1] f32, image_coords (unused),
    //                 camera_to_worlds[C,3,4] f32, intrinsics[C,3,3] f32
    const int*   pidx  = (const int*)d_in[0];
    const float* depth = (const float*)d_in[1];
    const float* c2w   = (const float*)d_in[3];
    const float* intr  = (const float*)d_in[4];
    float*       out   = (float*)d_out;

    int npoints  = in_sizes[0] / 3;
    int num_cams = in_sizes[3] / 12;
    if (num_cams > MAX_CAMS) num_cams = MAX_CAMS;

    int nchunks = (npoints + CHUNK - 1) / CHUNK;
    int blocks  = 148 * 5;
    int maxb    = (nchunks + WARPS - 1) / WARPS;
    if (blocks > maxb) blocks = maxb;
    point_gen_kernel<<<blocks, NTHREADS>>>(pidx, depth, c2w, intr, out,
                                           npoints, num_cams, nchunks);
}